// round 4
// baseline (speedup 1.0000x reference)
#include <cuda_runtime.h>
#include <cstdint>
#include <cstddef>

// Problem shape (fixed by the reference setup_inputs)
#define BB 64
#define TT 2048
#define NN 32
#define DD 8            // cp.async ring stages (distance 7 ≈ 1200 cyc > DRAM lat)
#define NTH 128
#define KNINF (-1e4f)
#define NEG_BIG (-3.402823466e38f)
#define LSEG 128
#define MAXSEG (TT / LSEG)   // 16

struct __align__(16) Smem {
    float tiles[DD][NN * NN];        // 32 KB, swizzled rows (see cOff below)
    float alpha[2][NN];              // double-buffered alpha
    unsigned char back[TT][NN];      // 64 KB backpointers
    unsigned char M[MAXSEG][NN];     // composed segment maps
    int entry[MAXSEG];               // tag at hi of each segment
    int misc[8];                     // [0..3] warp counts, [5] last_tag
};

__device__ __forceinline__ void cp16(unsigned dst, const void* src) {
    asm volatile("cp.async.cg.shared.global [%0], [%1], 16;" :: "r"(dst), "l"(src));
}
__device__ __forceinline__ void cp_commit() { asm volatile("cp.async.commit_group;"); }
template<int Nn> __device__ __forceinline__ void cp_wait() {
    asm volatile("cp.async.wait_group %0;" :: "n"(Nn));
}

__global__ void __launch_bounds__(NTH, 1)
viterbi_kernel(const float* __restrict__ lp, const int* __restrict__ mask,
               const int* __restrict__ startc, const int* __restrict__ endc,
               const int* __restrict__ transc, float* __restrict__ out)
{
    extern __shared__ __align__(16) char smraw[];
    Smem& sm = *reinterpret_cast<Smem*>(smraw);
    const int b    = blockIdx.x;
    const int tid  = threadIdx.x;
    const int w    = tid >> 5;        // warp id: owns columns j = 8w..8w+7
    const int lane = tid & 31;
    const int jloc = lane & 7;
    const int igrp = lane >> 3;       // i-group: i = 8*igrp .. 8*igrp+7
    const int j    = w * 8 + jloc;
    const int i0   = igrp * 8;

    // ---- sequence length (mask is prefix-true) ----
    int cnt = 0;
    #pragma unroll
    for (int t = tid; t < TT; t += NTH) cnt += (mask[b * TT + t] != 0);
    #pragma unroll
    for (int o = 16; o; o >>= 1) cnt += __shfl_xor_sync(0xffffffffu, cnt, o);
    if (lane == 0) sm.misc[w] = cnt;
    __syncthreads();
    const int len  = sm.misc[0] + sm.misc[1] + sm.misc[2] + sm.misc[3];
    const int last = len - 1;

    // ---- per-thread constants ----
    float tr[8];
    #pragma unroll
    for (int k = 0; k < 8; k++)
        tr[k] = transc[(i0 + k) * NN + j] ? 0.0f : KNINF;
    const float sp_j = startc[j] ? 0.0f : KNINF;
    const float ep_j = endc[j]   ? 0.0f : KNINF;

    const float* lpb = lp + (size_t)b * TT * NN * NN;

    // ---- cp.async slice: each thread copies two 16B chunks per tile ----
    // Swizzle: 16B-chunk cc of row r stored at byte r*128 + ((16*cc + 32*(r>>3)) & 127)
    // -> column reads below are 32-bank conflict-free with a per-thread constant offset.
    const int c2  = tid * 2;
    const int row = c2 >> 3;
    const int cc  = c2 & 7;
    const unsigned swz = (unsigned)((row >> 3) << 5);
    const unsigned dA  = (unsigned)(row * 128) + (((unsigned)(cc * 16)      + swz) & 127u);
    const unsigned dB  = (unsigned)(row * 128) + (((unsigned)(cc * 16 + 16) + swz) & 127u);
    const float* srcBase = lpb + row * NN + cc * 4;
    const unsigned tilesBase = (unsigned)__cvta_generic_to_shared(&sm.tiles[0][0]);
    // reader: element (i = i0+k, j) lives at tiles[stage][ (i0+k)*32 + cOff ]
    const int cOff = (j + 8 * igrp) & 31;

    // ---- prologue: issue tiles 0..DD-2 (one commit group per tile slot) ----
    for (int k = 0; k < DD - 1; k++) {
        if (k <= last) {
            unsigned sb = tilesBase + (unsigned)(k * (NN * NN * 4));
            const float* s0 = srcBase + (size_t)k * NN * NN;
            cp16(sb + dA, s0);
            cp16(sb + dB, s0 + 4);
        }
        cp_commit();
    }

    // ---- t = 0: alpha0[j] = max_i lp[0,i,j] + start_pen (+ end_pen if len==1) ----
    cp_wait<DD - 2>();
    __syncthreads();
    {
        const int ft = DD - 1;
        if (ft <= last) {
            unsigned sb = tilesBase + (unsigned)((ft % DD) * (NN * NN * 4));
            const float* s0 = srcBase + (size_t)ft * NN * NN;
            cp16(sb + dA, s0);
            cp16(sb + dB, s0 + 4);
        }
        cp_commit();

        const float* tile = sm.tiles[0];
        float best = NEG_BIG;
        #pragma unroll
        for (int k = 0; k < 8; k++)
            best = fmaxf(best, tile[(i0 + k) * NN + cOff]);
        best = fmaxf(best, __shfl_xor_sync(0xffffffffu, best, 8));
        best = fmaxf(best, __shfl_xor_sync(0xffffffffu, best, 16));
        if (igrp == 0) {
            float e = (last == 0) ? ep_j : 0.0f;
            sm.alpha[0][j] = (best + sp_j) + e;   // exact: const-in-i shift commutes with max
        }
    }

    // ---- main forward loop: ONE __syncthreads per step ----
    int p = 0;  // alpha[p] holds alpha_{t-1}
    for (int t = 1; t <= last; t++) {
        cp_wait<DD - 2>();
        __syncthreads();   // tile t visible everywhere; alpha(t-1) visible; stage (t-1)%DD free

        const int ft = t + DD - 1;
        if (ft <= last) {
            unsigned sb = tilesBase + (unsigned)((ft % DD) * (NN * NN * 4));
            const float* s0 = srcBase + (size_t)ft * NN * NN;
            cp16(sb + dA, s0);
            cp16(sb + dB, s0 + 4);
        }
        cp_commit();

        const float* tile = sm.tiles[t % DD];
        const float4 av0 = *reinterpret_cast<const float4*>(&sm.alpha[p][i0]);
        const float4 av1 = *reinterpret_cast<const float4*>(&sm.alpha[p][i0 + 4]);
        const float a[8] = {av0.x, av0.y, av0.z, av0.w, av1.x, av1.y, av1.z, av1.w};

        float best = NEG_BIG;
        int   bi   = 0;
        if (t != last) {
            #pragma unroll
            for (int k = 0; k < 8; k++) {
                float s = (tile[(i0 + k) * NN + cOff] + tr[k]) + a[k];
                if (s > best) { best = s; bi = i0 + k; }     // first-max (ascending i)
            }
        } else {
            #pragma unroll
            for (int k = 0; k < 8; k++) {   // peeled end step: ((phi+tr)+ep)+alpha
                float s = ((tile[(i0 + k) * NN + cOff] + tr[k]) + ep_j) + a[k];
                if (s > best) { best = s; bi = i0 + k; }
            }
        }
        // combine the 4 i-groups: prefer smaller i on exact tie (jnp.argmax semantics)
        float ob  = __shfl_xor_sync(0xffffffffu, best, 8);
        int   obi = __shfl_xor_sync(0xffffffffu, bi, 8);
        if (ob > best || (ob == best && obi < bi)) { best = ob; bi = obi; }
        ob  = __shfl_xor_sync(0xffffffffu, best, 16);
        obi = __shfl_xor_sync(0xffffffffu, bi, 16);
        if (ob > best || (ob == best && obi < bi)) { best = ob; bi = obi; }

        if (igrp == 0) {
            sm.alpha[p ^ 1][j] = best;
            sm.back[t][j] = (unsigned char)bi;
        }
        p ^= 1;
    }

    cp_wait<0>();
    __syncthreads();

    // ---- final max / argmax over tags (first occurrence) ----
    if (w == 0) {
        float v  = sm.alpha[p][lane];
        int  idx = lane;
        #pragma unroll
        for (int o = 16; o; o >>= 1) {
            float ov = __shfl_xor_sync(0xffffffffu, v, o);
            int   oi = __shfl_xor_sync(0xffffffffu, idx, o);
            if (ov > v || (ov == v && oi < idx)) { v = ov; idx = oi; }
        }
        if (lane == 0) { out[b] = v; sm.misc[5] = idx; }
    }
    __syncthreads();
    const int last_tag = sm.misc[5];

    float* tags = out + BB + (size_t)b * TT;
    for (int t = len + tid; t < TT; t += NTH) tags[t] = -1.0f;   // PADDING_INDEX

    if (last == 0) {
        if (tid == 0) tags[0] = (float)last_tag;
        return;
    }

    // ---- parallel backtrack: segment-composed pointer chase ----
    const int nseg = (last + LSEG - 1) / LSEG;
    for (int q = tid; q < nseg * NN; q += NTH) {
        const int s  = q >> 5;
        int y        = q & 31;
        const int lo = s * LSEG;
        const int hi = min((s + 1) * LSEG, last);
        for (int t = hi; t > lo; t--) y = sm.back[t][y];
        sm.M[s][q & 31] = (unsigned char)y;   // tag at lo given tag(hi)=x
    }
    __syncthreads();
    if (tid == 0) {
        int cur = last_tag;                   // tag at hi of top segment (== last)
        sm.entry[nseg - 1] = cur;
        for (int s = nseg - 1; s >= 1; s--) {
            cur = sm.M[s][cur];               // tag at lo_s == hi_{s-1}
            sm.entry[s - 1] = cur;
        }
        tags[0] = (float)sm.M[0][cur];        // cur == entry[0]; tag at position 0
    }
    __syncthreads();
    if (tid < nseg) {
        const int s  = tid;
        const int lo = s * LSEG;
        const int hi = min((s + 1) * LSEG, last);
        int cur = sm.entry[s];
        for (int t = hi; t > lo; t--) {
            tags[t] = (float)cur;
            cur = sm.back[t][cur];
        }
    }
}

extern "C" void kernel_launch(void* const* d_in, const int* in_sizes, int n_in,
                              void* d_out, int out_size)
{
    const float* lp   = (const float*)d_in[0];
    const int* mask   = (const int*)d_in[1];
    const int* startc = (const int*)d_in[2];
    const int* endc   = (const int*)d_in[3];
    const int* transc = (const int*)d_in[4];
    float* out = (float*)d_out;
    (void)in_sizes; (void)n_in; (void)out_size;

    const int smem_bytes = (int)sizeof(Smem);   // ~99 KB (< 227 KB limit)
    cudaFuncSetAttribute(viterbi_kernel,
                         cudaFuncAttributeMaxDynamicSharedMemorySize, smem_bytes);
    viterbi_kernel<<<BB, NTH, smem_bytes>>>(lp, mask, startc, endc, transc, out);
}